// round 2
// baseline (speedup 1.0000x reference)
#include <cuda_runtime.h>
#include <math.h>

// Shapes (fixed for this problem)
#define TOKS   4096      // B*S = 2*2048
#define DMODEL 1024
#define DFF    4096
#define SLEN   2048
#define NHEADS 16
#define HDIM   64
#define BATCH  2

// ---------------------------------------------------------------------------
// Scratch (device globals: allocation-free, graph-capture safe)
// ---------------------------------------------------------------------------
__device__ float g_qkv    [(size_t)TOKS * 3 * DMODEL];          // 48 MB
__device__ float g_scoresT[(size_t)BATCH * NHEADS * SLEN * SLEN]; // 512 MB: [z][s][t]
__device__ float g_post   [(size_t)TOKS * DMODEL];              // gelu(attn@V)/sqrt(S)
__device__ float g_attnout[(size_t)TOKS * DMODEL];
__device__ float g_x      [(size_t)TOKS * DMODEL];              // after LN1
__device__ float g_ff1    [(size_t)TOKS * DFF];                 // 64 MB
__device__ float g_ff2    [(size_t)TOKS * DMODEL];

__device__ __forceinline__ float gelu_exact(float x) {
    return 0.5f * x * (1.0f + erff(x * 0.70710678118654752440f));
}

// ---------------------------------------------------------------------------
// Generic NT SGEMM body: C[m,n] = alpha * sum_k A[m,k]*B[n,k] (+bias[n]) (+gelu)
// BM=BN=128, BK=8, 256 threads, 8x8 per thread. K % 8 == 0, M,N % 128 == 0.
// ---------------------------------------------------------------------------
template<int EPI>   // 0 = none, 1 = gelu
__device__ __forceinline__ void sgemm_nt_body(
    const float* __restrict__ A, int lda,
    const float* __restrict__ B, int ldb,
    float* __restrict__ C, int ldc,
    int K, float alpha, const float* __restrict__ bias)
{
    __shared__ float As[8][128];
    __shared__ float Bs[8][128];

    const int tid  = threadIdx.x;
    const int m0   = blockIdx.y * 128;
    const int n0   = blockIdx.x * 128;
    const int arow = tid >> 1;          // 0..127
    const int ac4  = (tid & 1) * 4;     // 0 or 4

    const float* Aptr = A + (long long)(m0 + arow) * lda + ac4;
    const float* Bptr = B + (long long)(n0 + arow) * ldb + ac4;

    float acc[8][8];
#pragma unroll
    for (int i = 0; i < 8; i++)
#pragma unroll
        for (int j = 0; j < 8; j++) acc[i][j] = 0.0f;

    const int tx = tid & 15;    // col group
    const int ty = tid >> 4;    // row group

    for (int k0 = 0; k0 < K; k0 += 8) {
        float4 av = *(const float4*)(Aptr + k0);
        float4 bv = *(const float4*)(Bptr + k0);
        __syncthreads();
        As[ac4 + 0][arow] = av.x; As[ac4 + 1][arow] = av.y;
        As[ac4 + 2][arow] = av.z; As[ac4 + 3][arow] = av.w;
        Bs[ac4 + 0][arow] = bv.x; Bs[ac4 + 1][arow] = bv.y;
        Bs[ac4 + 2][arow] = bv.z; Bs[ac4 + 3][arow] = bv.w;
        __syncthreads();
#pragma unroll
        for (int k = 0; k < 8; k++) {
            float a[8], b[8];
#pragma unroll
            for (int i = 0; i < 8; i++) a[i] = As[k][ty * 8 + i];
#pragma unroll
            for (int j = 0; j < 8; j++) b[j] = Bs[k][tx * 8 + j];
#pragma unroll
            for (int i = 0; i < 8; i++)
#pragma unroll
                for (int j = 0; j < 8; j++)
                    acc[i][j] = fmaf(a[i], b[j], acc[i][j]);
        }
    }

#pragma unroll
    for (int i = 0; i < 8; i++) {
        const int m = m0 + ty * 8 + i;
        float vals[8];
#pragma unroll
        for (int j = 0; j < 8; j++) {
            const int n = n0 + tx * 8 + j;
            float v = alpha * acc[i][j];
            if (bias) v += bias[n];
            if (EPI == 1) v = gelu_exact(v);
            vals[j] = v;
        }
        float* cp = C + (long long)m * ldc + n0 + tx * 8;
        *(float4*)(cp)     = make_float4(vals[0], vals[1], vals[2], vals[3]);
        *(float4*)(cp + 4) = make_float4(vals[4], vals[5], vals[6], vals[7]);
    }
}

template<int EPI>
__global__ __launch_bounds__(256) void k_sgemm(
    const float* __restrict__ A, int lda,
    const float* __restrict__ B, int ldb,
    float* __restrict__ C, int ldc,
    int K, float alpha, const float* __restrict__ bias)
{
    sgemm_nt_body<EPI>(A, lda, B, ldb, C, ldc, K, alpha, bias);
}

// ---------------------------------------------------------------------------
// scoresT[z][s][t] = scale * sum_e K[b,s,h,e] * Q[b,t,h,e]
// (stored s-major so softmax over t is over the contiguous axis)
// grid: (SLEN/128, SLEN/128, 32)
// ---------------------------------------------------------------------------
__global__ __launch_bounds__(256) void k_scores()
{
    const int z = blockIdx.z, b = z >> 4, h = z & 15;
    const float* Kb = g_qkv + (long long)b * SLEN * 3 * DMODEL + DMODEL + h * HDIM;
    const float* Qb = g_qkv + (long long)b * SLEN * 3 * DMODEL + h * HDIM;
    float* Cb = g_scoresT + (long long)z * SLEN * SLEN;
    sgemm_nt_body<0>(Kb, 3 * DMODEL, Qb, 3 * DMODEL, Cb, SLEN, HDIM, 0.125f, nullptr);
}

// ---------------------------------------------------------------------------
// Row softmax over t (contiguous, length 2048). One block per (z, s) row.
// ---------------------------------------------------------------------------
__global__ __launch_bounds__(256) void k_softmax()
{
    float* row = &g_scoresT[(size_t)blockIdx.x * SLEN];
    const int tid = threadIdx.x;
    __shared__ float red[256];

    float v[8];
    float mx = -INFINITY;
#pragma unroll
    for (int i = 0; i < 8; i++) { v[i] = row[tid + i * 256]; mx = fmaxf(mx, v[i]); }
    red[tid] = mx; __syncthreads();
    for (int s = 128; s > 0; s >>= 1) {
        if (tid < s) red[tid] = fmaxf(red[tid], red[tid + s]);
        __syncthreads();
    }
    mx = red[0]; __syncthreads();

    float sum = 0.0f;
#pragma unroll
    for (int i = 0; i < 8; i++) { v[i] = expf(v[i] - mx); sum += v[i]; }
    red[tid] = sum; __syncthreads();
    for (int s = 128; s > 0; s >>= 1) {
        if (tid < s) red[tid] += red[tid + s];
        __syncthreads();
    }
    const float inv = 1.0f / red[0];
#pragma unroll
    for (int i = 0; i < 8; i++) row[tid + i * 256] = v[i] * inv;
}

// ---------------------------------------------------------------------------
// post[b,t,h,:] = gelu( sum_s attnT[z][s][t] * V[b,s,h,:] ) / sqrt(S)
// TN GEMM: BM=128 (t), BN=64 (e), BK=16 (s). grid: (SLEN/128, 1, 32)
// ---------------------------------------------------------------------------
__global__ __launch_bounds__(256) void k_av()
{
    __shared__ float As[16][128];
    __shared__ float Bs[16][64];

    const int z = blockIdx.z, b = z >> 4, h = z & 15;
    const float* A = g_scoresT + (long long)z * SLEN * SLEN;                  // [s][t], ld SLEN
    const float* V = g_qkv + (long long)b * SLEN * 3 * DMODEL + 2 * DMODEL + h * HDIM; // [s][e], ld 3*DMODEL
    float* C = g_post + (long long)b * SLEN * DMODEL + h * HDIM;              // [t][e], ld DMODEL

    const int m0  = blockIdx.x * 128;
    const int tid = threadIdx.x;
    const int tx  = tid & 15;   // e group: cols tx*4..tx*4+3
    const int ty  = tid >> 4;   // t group: rows ty*8..ty*8+7

    // load index precompute
    const int kk0 = tid >> 5,         m4a = (tid & 31) * 4;
    const int kk1 = (tid + 256) >> 5, m4b = ((tid + 256) & 31) * 4;
    const int kkb = tid >> 4,         n4  = (tid & 15) * 4;

    float acc[8][4];
#pragma unroll
    for (int i = 0; i < 8; i++)
#pragma unroll
        for (int j = 0; j < 4; j++) acc[i][j] = 0.0f;

    for (int k0 = 0; k0 < SLEN; k0 += 16) {
        float4 a0 = *(const float4*)(A + (long long)(k0 + kk0) * SLEN + m0 + m4a);
        float4 a1 = *(const float4*)(A + (long long)(k0 + kk1) * SLEN + m0 + m4b);
        float4 bv = *(const float4*)(V + (long long)(k0 + kkb) * (3 * DMODEL) + n4);
        __syncthreads();
        As[kk0][m4a + 0] = a0.x; As[kk0][m4a + 1] = a0.y; As[kk0][m4a + 2] = a0.z; As[kk0][m4a + 3] = a0.w;
        As[kk1][m4b + 0] = a1.x; As[kk1][m4b + 1] = a1.y; As[kk1][m4b + 2] = a1.z; As[kk1][m4b + 3] = a1.w;
        Bs[kkb][n4 + 0] = bv.x; Bs[kkb][n4 + 1] = bv.y; Bs[kkb][n4 + 2] = bv.z; Bs[kkb][n4 + 3] = bv.w;
        __syncthreads();
#pragma unroll
        for (int kk = 0; kk < 16; kk++) {
            float a[8], bb[4];
#pragma unroll
            for (int i = 0; i < 8; i++) a[i] = As[kk][ty * 8 + i];
#pragma unroll
            for (int j = 0; j < 4; j++) bb[j] = Bs[kk][tx * 4 + j];
#pragma unroll
            for (int i = 0; i < 8; i++)
#pragma unroll
                for (int j = 0; j < 4; j++)
                    acc[i][j] = fmaf(a[i], bb[j], acc[i][j]);
        }
    }

    const float inv_sqrt_s = 0.022097086912079608f; // 1/sqrt(2048)
#pragma unroll
    for (int i = 0; i < 8; i++) {
        const int t = m0 + ty * 8 + i;
        float4 o;
        o.x = gelu_exact(acc[i][0]) * inv_sqrt_s;
        o.y = gelu_exact(acc[i][1]) * inv_sqrt_s;
        o.z = gelu_exact(acc[i][2]) * inv_sqrt_s;
        o.w = gelu_exact(acc[i][3]) * inv_sqrt_s;
        *(float4*)(C + (long long)t * DMODEL + tx * 4) = o;
    }
}

// ---------------------------------------------------------------------------
// out[r,:] = LayerNorm(x1[r,:] + x2[r,:]) * g + b    (row length 1024)
// ---------------------------------------------------------------------------
__global__ __launch_bounds__(256) void k_add_ln(
    const float* __restrict__ x1, const float* __restrict__ x2,
    const float* __restrict__ gg, const float* __restrict__ bb,
    float* __restrict__ out)
{
    const long long base = (long long)blockIdx.x * DMODEL;
    const int tid = threadIdx.x;
    __shared__ float rs[256], rs2[256];

    float v[4];
    float s = 0.0f, s2 = 0.0f;
#pragma unroll
    for (int i = 0; i < 4; i++) {
        const int c = tid + i * 256;
        const float a = x1[base + c] + x2[base + c];
        v[i] = a; s += a; s2 += a * a;
    }
    rs[tid] = s; rs2[tid] = s2; __syncthreads();
    for (int st = 128; st > 0; st >>= 1) {
        if (tid < st) { rs[tid] += rs[tid + st]; rs2[tid] += rs2[tid + st]; }
        __syncthreads();
    }
    const float mu  = rs[0] * (1.0f / DMODEL);
    const float var = rs2[0] * (1.0f / DMODEL) - mu * mu;
    const float r   = rsqrtf(var + 1e-5f);
#pragma unroll
    for (int i = 0; i < 4; i++) {
        const int c = tid + i * 256;
        out[base + c] = (v[i] - mu) * r * gg[c] + bb[c];
    }
}

// ---------------------------------------------------------------------------
// Launch
// ---------------------------------------------------------------------------
extern "C" void kernel_launch(void* const* d_in, const int* in_sizes, int n_in,
                              void* d_out, int out_size)
{
    (void)in_sizes; (void)n_in; (void)out_size;
    const float* src       = (const float*)d_in[0];
    const float* in_proj_w = (const float*)d_in[1];
    const float* in_proj_b = (const float*)d_in[2];
    const float* out_w     = (const float*)d_in[3];
    const float* out_b     = (const float*)d_in[4];
    const float* lin1_w    = (const float*)d_in[5];
    const float* lin1_b    = (const float*)d_in[6];
    const float* lin2_w    = (const float*)d_in[7];
    const float* lin2_b    = (const float*)d_in[8];
    const float* ln1_g     = (const float*)d_in[9];
    const float* ln1_bb    = (const float*)d_in[10];
    const float* ln2_g     = (const float*)d_in[11];
    const float* ln2_bb    = (const float*)d_in[12];
    float* out = (float*)d_out;

    float *qkv, *post, *attnout, *x, *ff1, *ff2;
    cudaGetSymbolAddress((void**)&qkv,     g_qkv);
    cudaGetSymbolAddress((void**)&post,    g_post);
    cudaGetSymbolAddress((void**)&attnout, g_attnout);
    cudaGetSymbolAddress((void**)&x,       g_x);
    cudaGetSymbolAddress((void**)&ff1,     g_ff1);
    cudaGetSymbolAddress((void**)&ff2,     g_ff2);

    const dim3 blk(256);

    // 1. QKV projection: [4096,1024] @ [1024,3072]^T
    k_sgemm<0><<<dim3(3 * DMODEL / 128, TOKS / 128), blk>>>(
        src, DMODEL, in_proj_w, DMODEL, qkv, 3 * DMODEL, DMODEL, 1.0f, in_proj_b);

    // 2. scoresT[z][s][t] = scale * K·Q^T (batched over 32 heads)
    k_scores<<<dim3(SLEN / 128, SLEN / 128, BATCH * NHEADS), blk>>>();

    // 3. softmax over t (contiguous rows)
    k_softmax<<<BATCH * NHEADS * SLEN, 256>>>();

    // 4. post = gelu(attnT^T @ V) / sqrt(S)
    k_av<<<dim3(SLEN / 128, 1, BATCH * NHEADS), blk>>>();

    // 5. attn output projection
    k_sgemm<0><<<dim3(DMODEL / 128, TOKS / 128), blk>>>(
        post, DMODEL, out_w, DMODEL, attnout, DMODEL, DMODEL, 1.0f, out_b);

    // 6. x = LN1(src + attnout)
    k_add_ln<<<TOKS, 256>>>(src, attnout, ln1_g, ln1_bb, x);

    // 7. ff1 = gelu(x @ lin1_w^T + b)
    k_sgemm<1><<<dim3(DFF / 128, TOKS / 128), blk>>>(
        x, DMODEL, lin1_w, DMODEL, ff1, DFF, DMODEL, 1.0f, lin1_b);

    // 8. ff2 = ff1 @ lin2_w^T + b
    k_sgemm<0><<<dim3(DMODEL / 128, TOKS / 128), blk>>>(
        ff1, DFF, lin2_w, DFF, ff2, DMODEL, DFF, 1.0f, lin2_b);

    // 9. out = LN2(x + ff2)
    k_add_ln<<<TOKS, 256>>>(x, ff2, ln2_g, ln2_bb, out);
}

// round 3
// speedup vs baseline: 2.3478x; 2.3478x over previous
#include <cuda_runtime.h>
#include <math.h>

// Shapes (fixed)
#define TOKS   4096
#define DMODEL 1024
#define DFF    4096
#define SLEN   2048
#define NHEADS 16
#define HDIM   64
#define BATCH  2
#define BK     16

// ---------------------------------------------------------------------------
// Scratch
// ---------------------------------------------------------------------------
__device__ float g_qkv    [(size_t)TOKS * 3 * DMODEL];
__device__ float g_scoresT[(size_t)BATCH * NHEADS * SLEN * SLEN]; // [z][s][t]
__device__ float g_post   [(size_t)TOKS * DMODEL];
__device__ float g_attnout[(size_t)TOKS * DMODEL];
__device__ float g_x      [(size_t)TOKS * DMODEL];
__device__ float g_ff1    [(size_t)TOKS * DFF];
__device__ float g_ff2    [(size_t)TOKS * DMODEL];

__device__ __forceinline__ float gelu_exact(float x) {
    return 0.5f * x * (1.0f + erff(x * 0.70710678118654752440f));
}
__device__ __forceinline__ float tf32r(float x) {
    float y; asm("cvt.rna.tf32.f32 %0, %1;" : "=f"(y) : "f"(x)); return y;
}
__device__ __forceinline__ float4 cvt4(float4 v) {
    return make_float4(tf32r(v.x), tf32r(v.y), tf32r(v.z), tf32r(v.w));
}
__device__ __forceinline__ unsigned sptr(const void* p) {
    return (unsigned)__cvta_generic_to_shared(p);
}
__device__ __forceinline__ void ldsm4(unsigned& d0, unsigned& d1, unsigned& d2, unsigned& d3,
                                      unsigned addr) {
    asm volatile("ldmatrix.sync.aligned.m8n8.x4.shared.b16 {%0,%1,%2,%3}, [%4];"
                 : "=r"(d0), "=r"(d1), "=r"(d2), "=r"(d3) : "r"(addr));
}
__device__ __forceinline__ void mma8(float* c, const unsigned* a, const unsigned* b) {
    asm volatile("mma.sync.aligned.m16n8k8.row.col.f32.tf32.tf32.f32 "
                 "{%0,%1,%2,%3}, {%4,%5,%6,%7}, {%8,%9}, {%0,%1,%2,%3};"
                 : "+f"(c[0]), "+f"(c[1]), "+f"(c[2]), "+f"(c[3])
                 : "r"(a[0]), "r"(a[1]), "r"(a[2]), "r"(a[3]), "r"(b[0]), "r"(b[1]));
}

// ---------------------------------------------------------------------------
// NT tensor-core GEMM body: C[m,n] = epi( sum_k A[m,k]*B[n,k] )
// BM=BN=128, BK=16, 256 thr = 8 warps (2m x 4n), warp tile 64x32.
// EPI: 0: +bias ; 1: gelu(+bias) ; 2: *alpha
// ---------------------------------------------------------------------------
template<int EPI>
__device__ __forceinline__ void tc_nt_body(
    const float* __restrict__ A, int lda,
    const float* __restrict__ B, int ldb,
    float* __restrict__ C, int ldc,
    int K, float alpha, const float* __restrict__ bias,
    int m0, int n0)
{
    constexpr int P = 20;               // pad: 16B-aligned rows, bank spread
    __shared__ float As[128 * P];
    __shared__ float Bs[128 * P];

    const int tid = threadIdx.x;
    const int w = tid >> 5, L = tid & 31;
    const int wm = w & 1, wn = w >> 1;
    const int mwb = wm * 64, nwb = wn * 32;

    const int lrow = tid >> 1;
    const int lcol = (tid & 1) * 8;
    const float* Ap = A + (long long)(m0 + lrow) * lda + lcol;
    const float* Bp = B + (long long)(n0 + lrow) * ldb + lcol;

    float4 ra0 = *(const float4*)(Ap);
    float4 ra1 = *(const float4*)(Ap + 4);
    float4 rb0 = *(const float4*)(Bp);
    float4 rb1 = *(const float4*)(Bp + 4);
    Ap += BK; Bp += BK;

    float acc[4][4][4];
#pragma unroll
    for (int i = 0; i < 4; i++)
#pragma unroll
        for (int j = 0; j < 4; j++)
#pragma unroll
            for (int r = 0; r < 4; r++) acc[i][j][r] = 0.0f;

    const int kiters = K / BK;
    for (int it = 0; it < kiters; it++) {
        __syncthreads();
        float* as = &As[lrow * P + lcol];
        *(float4*)(as)     = cvt4(ra0);
        *(float4*)(as + 4) = cvt4(ra1);
        float* bs = &Bs[lrow * P + lcol];
        *(float4*)(bs)     = cvt4(rb0);
        *(float4*)(bs + 4) = cvt4(rb1);
        __syncthreads();

        if (it + 1 < kiters) {
            ra0 = *(const float4*)(Ap);
            ra1 = *(const float4*)(Ap + 4);
            rb0 = *(const float4*)(Bp);
            rb1 = *(const float4*)(Bp + 4);
            Ap += BK; Bp += BK;
        }

#pragma unroll
        for (int ks = 0; ks < 2; ks++) {
            unsigned Af[4][4], Bf[4][2];
#pragma unroll
            for (int mt = 0; mt < 4; mt++) {
                unsigned ad = sptr(&As[(mwb + mt * 16 + (L & 15)) * P + ks * 8 + (L >> 4) * 4]);
                ldsm4(Af[mt][0], Af[mt][1], Af[mt][2], Af[mt][3], ad);
            }
#pragma unroll
            for (int np = 0; np < 2; np++) {
                unsigned bd = sptr(&Bs[(nwb + np * 16 + (L & 7) + ((L >> 4) << 3)) * P
                                       + ks * 8 + ((L >> 3) & 1) * 4]);
                ldsm4(Bf[2 * np][0], Bf[2 * np][1], Bf[2 * np + 1][0], Bf[2 * np + 1][1], bd);
            }
#pragma unroll
            for (int mt = 0; mt < 4; mt++)
#pragma unroll
                for (int nt = 0; nt < 4; nt++)
                    mma8(acc[mt][nt], Af[mt], Bf[nt]);
        }
    }

    const int g = L >> 2, tig = L & 3;
#pragma unroll
    for (int mt = 0; mt < 4; mt++) {
        const int r0 = m0 + mwb + mt * 16 + g;
#pragma unroll
        for (int nt = 0; nt < 4; nt++) {
            const int c = n0 + nwb + nt * 8 + tig * 2;
            float v0 = acc[mt][nt][0], v1 = acc[mt][nt][1];
            float v2 = acc[mt][nt][2], v3 = acc[mt][nt][3];
            if (EPI == 0) {
                v0 += bias[c]; v1 += bias[c + 1]; v2 += bias[c]; v3 += bias[c + 1];
            } else if (EPI == 1) {
                v0 = gelu_exact(v0 + bias[c]);     v1 = gelu_exact(v1 + bias[c + 1]);
                v2 = gelu_exact(v2 + bias[c]);     v3 = gelu_exact(v3 + bias[c + 1]);
            } else { // EPI == 2
                v0 *= alpha; v1 *= alpha; v2 *= alpha; v3 *= alpha;
            }
            *(float2*)(C + (long long)r0 * ldc + c)       = make_float2(v0, v1);
            *(float2*)(C + (long long)(r0 + 8) * ldc + c) = make_float2(v2, v3);
        }
    }
}

// ---------------------------------------------------------------------------
// TN tensor-core GEMM body (both operands k-major): C[m,n] = sum_k A[k,m]*B[k,n]
// BM=128, BN=64, BK=16. SMEM staged k-major, conflict-free scalar fragment LDS.
// EPI 3: gelu(v) * alpha
// ---------------------------------------------------------------------------
__device__ __forceinline__ void tc_tn_body(
    const float* __restrict__ A, int lda,   // A[k][m]
    const float* __restrict__ B, int ldb,   // B[k][n], n in [0,64)
    float* __restrict__ C, int ldc,
    int K, float alpha, int m0)
{
    constexpr int AP = 136;   // 128 + 8: tig*136 % 32 = 8*tig -> conflict-free
    constexpr int BP = 72;    // 64 + 8
    __shared__ float As[BK * AP];
    __shared__ float Bs[BK * BP];

    const int tid = threadIdx.x;
    const int w = tid >> 5, L = tid & 31;
    const int wm = w & 1, wn = w >> 1;
    const int mwb = wm * 64, nwb = wn * 16;

    const int lk  = tid >> 4;          // 0..15
    const int lm4 = (tid & 15) * 4;    // 0..60
    const float* Ap = A + (long long)lk * lda + m0 + lm4;
    const float* Bp = B + (long long)lk * ldb + lm4;

    float4 ra0 = *(const float4*)(Ap);
    float4 ra1 = *(const float4*)(Ap + 64);
    float4 rb0 = *(const float4*)(Bp);
    Ap += (long long)BK * lda; Bp += (long long)BK * ldb;

    float acc[4][2][4];
#pragma unroll
    for (int i = 0; i < 4; i++)
#pragma unroll
        for (int j = 0; j < 2; j++)
#pragma unroll
            for (int r = 0; r < 4; r++) acc[i][j][r] = 0.0f;

    const int g = L >> 2, tig = L & 3;
    const int kiters = K / BK;
    for (int it = 0; it < kiters; it++) {
        __syncthreads();
        float* as = &As[lk * AP + lm4];
        *(float4*)(as)      = cvt4(ra0);
        *(float4*)(as + 64) = cvt4(ra1);
        *(float4*)(&Bs[lk * BP + lm4]) = cvt4(rb0);
        __syncthreads();

        if (it + 1 < kiters) {
            ra0 = *(const float4*)(Ap);
            ra1 = *(const float4*)(Ap + 64);
            rb0 = *(const float4*)(Bp);
            Ap += (long long)BK * lda; Bp += (long long)BK * ldb;
        }

#pragma unroll
        for (int ks = 0; ks < 2; ks++) {
            const unsigned* asb = (const unsigned*)&As[(ks * 8 + tig) * AP];
            const unsigned* bsb = (const unsigned*)&Bs[(ks * 8 + tig) * BP];
            unsigned Af[4][4], Bf[2][2];
#pragma unroll
            for (int mt = 0; mt < 4; mt++) {
                const int mb = mwb + mt * 16 + g;
                Af[mt][0] = asb[mb];
                Af[mt][1] = asb[mb + 8];
                Af[mt][2] = asb[mb + 4 * AP];
                Af[mt][3] = asb[mb + 4 * AP + 8];
            }
#pragma unroll
            for (int nt = 0; nt < 2; nt++) {
                const int nb = nwb + nt * 8 + g;
                Bf[nt][0] = bsb[nb];
                Bf[nt][1] = bsb[nb + 4 * BP];
            }
#pragma unroll
            for (int mt = 0; mt < 4; mt++)
#pragma unroll
                for (int nt = 0; nt < 2; nt++)
                    mma8(acc[mt][nt], Af[mt], Bf[nt]);
        }
    }

#pragma unroll
    for (int mt = 0; mt < 4; mt++) {
        const int r0 = m0 + mwb + mt * 16 + g;
#pragma unroll
        for (int nt = 0; nt < 2; nt++) {
            const int c = nwb + nt * 8 + tig * 2;
            float v0 = gelu_exact(acc[mt][nt][0]) * alpha;
            float v1 = gelu_exact(acc[mt][nt][1]) * alpha;
            float v2 = gelu_exact(acc[mt][nt][2]) * alpha;
            float v3 = gelu_exact(acc[mt][nt][3]) * alpha;
            *(float2*)(C + (long long)r0 * ldc + c)       = make_float2(v0, v1);
            *(float2*)(C + (long long)(r0 + 8) * ldc + c) = make_float2(v2, v3);
        }
    }
}

// ---------------------------------------------------------------------------
// Kernel wrappers
// ---------------------------------------------------------------------------
__global__ __launch_bounds__(256) void k_tc_bias(
    const float* __restrict__ A, int lda, const float* __restrict__ B, int ldb,
    float* __restrict__ C, int ldc, int K, const float* __restrict__ bias)
{
    tc_nt_body<0>(A, lda, B, ldb, C, ldc, K, 1.0f, bias,
                  blockIdx.y * 128, blockIdx.x * 128);
}

__global__ __launch_bounds__(256) void k_tc_bias_gelu(
    const float* __restrict__ A, int lda, const float* __restrict__ B, int ldb,
    float* __restrict__ C, int ldc, int K, const float* __restrict__ bias)
{
    tc_nt_body<1>(A, lda, B, ldb, C, ldc, K, 1.0f, bias,
                  blockIdx.y * 128, blockIdx.x * 128);
}

__global__ __launch_bounds__(256) void k_tc_scores()
{
    const int z = blockIdx.z, b = z >> 4, h = z & 15;
    const float* Kb = g_qkv + (long long)b * SLEN * 3 * DMODEL + DMODEL + h * HDIM;
    const float* Qb = g_qkv + (long long)b * SLEN * 3 * DMODEL + h * HDIM;
    float* Cb = g_scoresT + (long long)z * SLEN * SLEN;
    tc_nt_body<2>(Kb, 3 * DMODEL, Qb, 3 * DMODEL, Cb, SLEN, HDIM, 0.125f, nullptr,
                  blockIdx.y * 128, blockIdx.x * 128);
}

__global__ __launch_bounds__(256) void k_tc_av()
{
    const int z = blockIdx.z, b = z >> 4, h = z & 15;
    const float* A = g_scoresT + (long long)z * SLEN * SLEN;                      // [s][t]
    const float* V = g_qkv + (long long)b * SLEN * 3 * DMODEL + 2 * DMODEL + h * HDIM; // [s][e]
    float* C = g_post + (long long)b * SLEN * DMODEL + h * HDIM;                  // [t][e]
    tc_tn_body(A, SLEN, V, 3 * DMODEL, C, DMODEL, SLEN,
               0.022097086912079608f /* 1/sqrt(2048) */, blockIdx.x * 128);
}

// ---------------------------------------------------------------------------
// Row softmax over t (contiguous, length 2048). One block per (z, s) row.
// ---------------------------------------------------------------------------
__global__ __launch_bounds__(256) void k_softmax()
{
    float* row = &g_scoresT[(size_t)blockIdx.x * SLEN];
    const int tid = threadIdx.x;
    __shared__ float red[256];

    float v[8];
    float mx = -INFINITY;
#pragma unroll
    for (int i = 0; i < 8; i++) { v[i] = row[tid + i * 256]; mx = fmaxf(mx, v[i]); }
    red[tid] = mx; __syncthreads();
    for (int s = 128; s > 0; s >>= 1) {
        if (tid < s) red[tid] = fmaxf(red[tid], red[tid + s]);
        __syncthreads();
    }
    mx = red[0]; __syncthreads();

    float sum = 0.0f;
#pragma unroll
    for (int i = 0; i < 8; i++) { v[i] = expf(v[i] - mx); sum += v[i]; }
    red[tid] = sum; __syncthreads();
    for (int s = 128; s > 0; s >>= 1) {
        if (tid < s) red[tid] += red[tid + s];
        __syncthreads();
    }
    const float inv = 1.0f / red[0];
#pragma unroll
    for (int i = 0; i < 8; i++) row[tid + i * 256] = v[i] * inv;
}

// ---------------------------------------------------------------------------
// out[r,:] = LayerNorm(x1[r,:] + x2[r,:]) * g + b
// ---------------------------------------------------------------------------
__global__ __launch_bounds__(256) void k_add_ln(
    const float* __restrict__ x1, const float* __restrict__ x2,
    const float* __restrict__ gg, const float* __restrict__ bb,
    float* __restrict__ out)
{
    const long long base = (long long)blockIdx.x * DMODEL;
    const int tid = threadIdx.x;
    __shared__ float rs[256], rs2[256];

    float v[4];
    float s = 0.0f, s2 = 0.0f;
#pragma unroll
    for (int i = 0; i < 4; i++) {
        const int c = tid + i * 256;
        const float a = x1[base + c] + x2[base + c];
        v[i] = a; s += a; s2 += a * a;
    }
    rs[tid] = s; rs2[tid] = s2; __syncthreads();
    for (int st = 128; st > 0; st >>= 1) {
        if (tid < st) { rs[tid] += rs[tid + st]; rs2[tid] += rs2[tid + st]; }
        __syncthreads();
    }
    const float mu  = rs[0] * (1.0f / DMODEL);
    const float var = rs2[0] * (1.0f / DMODEL) - mu * mu;
    const float r   = rsqrtf(var + 1e-5f);
#pragma unroll
    for (int i = 0; i < 4; i++) {
        const int c = tid + i * 256;
        out[base + c] = (v[i] - mu) * r * gg[c] + bb[c];
    }
}

// ---------------------------------------------------------------------------
// Launch
// ---------------------------------------------------------------------------
extern "C" void kernel_launch(void* const* d_in, const int* in_sizes, int n_in,
                              void* d_out, int out_size)
{
    (void)in_sizes; (void)n_in; (void)out_size;
    const float* src       = (const float*)d_in[0];
    const float* in_proj_w = (const float*)d_in[1];
    const float* in_proj_b = (const float*)d_in[2];
    const float* out_w     = (const float*)d_in[3];
    const float* out_b     = (const float*)d_in[4];
    const float* lin1_w    = (const float*)d_in[5];
    const float* lin1_b    = (const float*)d_in[6];
    const float* lin2_w    = (const float*)d_in[7];
    const float* lin2_b    = (const float*)d_in[8];
    const float* ln1_g     = (const float*)d_in[9];
    const float* ln1_bb    = (const float*)d_in[10];
    const float* ln2_g     = (const float*)d_in[11];
    const float* ln2_bb    = (const float*)d_in[12];
    float* out = (float*)d_out;

    float *qkv, *post, *attnout, *x, *ff1, *ff2;
    cudaGetSymbolAddress((void**)&qkv,     g_qkv);
    cudaGetSymbolAddress((void**)&post,    g_post);
    cudaGetSymbolAddress((void**)&attnout, g_attnout);
    cudaGetSymbolAddress((void**)&x,       g_x);
    cudaGetSymbolAddress((void**)&ff1,     g_ff1);
    cudaGetSymbolAddress((void**)&ff2,     g_ff2);

    const dim3 blk(256);

    // 1. QKV projection
    k_tc_bias<<<dim3(3 * DMODEL / 128, TOKS / 128), blk>>>(
        src, DMODEL, in_proj_w, DMODEL, qkv, 3 * DMODEL, DMODEL, in_proj_b);

    // 2. scoresT = scale * K @ Q^T  (batched over 32 (b,h))
    k_tc_scores<<<dim3(SLEN / 128, SLEN / 128, BATCH * NHEADS), blk>>>();

    // 3. softmax over t
    k_softmax<<<BATCH * NHEADS * SLEN, 256>>>();

    // 4. post = gelu(attnT^T @ V) / sqrt(S)
    k_tc_av<<<dim3(SLEN / 128, 1, BATCH * NHEADS), blk>>>();

    // 5. attn output projection
    k_tc_bias<<<dim3(DMODEL / 128, TOKS / 128), blk>>>(
        post, DMODEL, out_w, DMODEL, attnout, DMODEL, DMODEL, out_b);

    // 6. x = LN1(src + attnout)
    k_add_ln<<<TOKS, 256>>>(src, attnout, ln1_g, ln1_bb, x);

    // 7. ff1 = gelu(x @ lin1_w^T + b)
    k_tc_bias_gelu<<<dim3(DFF / 128, TOKS / 128), blk>>>(
        x, DMODEL, lin1_w, DMODEL, ff1, DFF, DMODEL, lin1_b);

    // 8. ff2 = ff1 @ lin2_w^T + b
    k_tc_bias<<<dim3(DMODEL / 128, TOKS / 128), blk>>>(
        ff1, DFF, lin2_w, DFF, ff2, DMODEL, DFF, lin2_b);

    // 9. out = LN2(x + ff2)
    k_add_ln<<<TOKS, 256>>>(x, ff2, ln2_g, ln2_bb, out);
}

// round 5
// speedup vs baseline: 2.6794x; 1.1413x over previous
#include <cuda_runtime.h>
#include <math.h>

// Shapes (fixed)
#define TOKS   4096
#define DMODEL 1024
#define DFF    4096
#define SLEN   2048
#define NHEADS 16
#define HDIM   64
#define BATCH  2
#define BK     16

// ---------------------------------------------------------------------------
// Scratch
// ---------------------------------------------------------------------------
__device__ float  g_qkv    [(size_t)TOKS * 3 * DMODEL];
__device__ float  g_post   [(size_t)TOKS * DMODEL];
__device__ float  g_attnout[(size_t)TOKS * DMODEL];
__device__ float  g_x      [(size_t)TOKS * DMODEL];
__device__ float  g_ff1    [(size_t)TOKS * DFF];
__device__ float  g_ff2    [(size_t)TOKS * DMODEL];
__device__ float2 g_stats  [(size_t)BATCH * NHEADS * SLEN];   // (m_s, Z_s)

__device__ __forceinline__ float gelu_exact(float x) {
    return 0.5f * x * (1.0f + erff(x * 0.70710678118654752440f));
}
__device__ __forceinline__ float tf32r(float x) {
    float y; asm("cvt.rna.tf32.f32 %0, %1;" : "=f"(y) : "f"(x)); return y;
}
__device__ __forceinline__ float4 cvt4(float4 v) {
    return make_float4(tf32r(v.x), tf32r(v.y), tf32r(v.z), tf32r(v.w));
}
__device__ __forceinline__ unsigned sptr(const void* p) {
    return (unsigned)__cvta_generic_to_shared(p);
}
__device__ __forceinline__ void ldsm4(unsigned& d0, unsigned& d1, unsigned& d2, unsigned& d3,
                                      unsigned addr) {
    asm volatile("ldmatrix.sync.aligned.m8n8.x4.shared.b16 {%0,%1,%2,%3}, [%4];"
                 : "=r"(d0), "=r"(d1), "=r"(d2), "=r"(d3) : "r"(addr));
}
__device__ __forceinline__ void mma8(float* c, const unsigned* a, const unsigned* b) {
    asm volatile("mma.sync.aligned.m16n8k8.row.col.f32.tf32.tf32.f32 "
                 "{%0,%1,%2,%3}, {%4,%5,%6,%7}, {%8,%9}, {%0,%1,%2,%3};"
                 : "+f"(c[0]), "+f"(c[1]), "+f"(c[2]), "+f"(c[3])
                 : "r"(a[0]), "r"(a[1]), "r"(a[2]), "r"(a[3]), "r"(b[0]), "r"(b[1]));
}
__device__ __forceinline__ float qmax(float v) {
    v = fmaxf(v, __shfl_xor_sync(0xffffffffu, v, 1));
    v = fmaxf(v, __shfl_xor_sync(0xffffffffu, v, 2));
    return v;
}
__device__ __forceinline__ float qsum(float v) {
    v += __shfl_xor_sync(0xffffffffu, v, 1);
    v += __shfl_xor_sync(0xffffffffu, v, 2);
    return v;
}

// ---------------------------------------------------------------------------
// NT tensor-core GEMM, double-buffered SMEM.
// C[m,n] = epi( sum_k A[m,k]*B[n,k] ); BM=BN=128, BK=16, 8 warps (2m x 4n).
// EPI: 0 = +bias ; 1 = gelu(+bias)
// ---------------------------------------------------------------------------
template<int EPI>
__device__ __forceinline__ void tc_nt_body(
    const float* __restrict__ A, int lda,
    const float* __restrict__ B, int ldb,
    float* __restrict__ C, int ldc,
    int K, const float* __restrict__ bias,
    int m0, int n0)
{
    constexpr int P = 20;
    __shared__ float As[2][128 * P];
    __shared__ float Bs[2][128 * P];

    const int tid = threadIdx.x;
    const int w = tid >> 5, L = tid & 31;
    const int wm = w & 1, wn = w >> 1;
    const int mwb = wm * 64, nwb = wn * 32;

    const int lrow = tid >> 1;
    const int lcol = (tid & 1) * 8;
    const float* Ap = A + (long long)(m0 + lrow) * lda + lcol;
    const float* Bp = B + (long long)(n0 + lrow) * ldb + lcol;

    float4 ra0 = *(const float4*)(Ap);
    float4 ra1 = *(const float4*)(Ap + 4);
    float4 rb0 = *(const float4*)(Bp);
    float4 rb1 = *(const float4*)(Bp + 4);
    Ap += BK; Bp += BK;

    // stage tile 0
    {
        float* as = &As[0][lrow * P + lcol];
        *(float4*)(as)     = cvt4(ra0);
        *(float4*)(as + 4) = cvt4(ra1);
        float* bs = &Bs[0][lrow * P + lcol];
        *(float4*)(bs)     = cvt4(rb0);
        *(float4*)(bs + 4) = cvt4(rb1);
    }

    float acc[4][4][4];
#pragma unroll
    for (int i = 0; i < 4; i++)
#pragma unroll
        for (int j = 0; j < 4; j++)
#pragma unroll
            for (int r = 0; r < 4; r++) acc[i][j][r] = 0.0f;

    const int kiters = K / BK;
    for (int it = 0; it < kiters; it++) {
        __syncthreads();
        const bool more = (it + 1 < kiters);
        if (more) {
            ra0 = *(const float4*)(Ap);
            ra1 = *(const float4*)(Ap + 4);
            rb0 = *(const float4*)(Bp);
            rb1 = *(const float4*)(Bp + 4);
            Ap += BK; Bp += BK;
        }

        const float* Ab = As[it & 1];
        const float* Bb = Bs[it & 1];
#pragma unroll
        for (int ks = 0; ks < 2; ks++) {
            unsigned Af[4][4], Bf[4][2];
#pragma unroll
            for (int mt = 0; mt < 4; mt++) {
                unsigned ad = sptr(&Ab[(mwb + mt * 16 + (L & 15)) * P + ks * 8 + (L >> 4) * 4]);
                ldsm4(Af[mt][0], Af[mt][1], Af[mt][2], Af[mt][3], ad);
            }
#pragma unroll
            for (int np = 0; np < 2; np++) {
                unsigned bd = sptr(&Bb[(nwb + np * 16 + (L & 7) + ((L >> 4) << 3)) * P
                                       + ks * 8 + ((L >> 3) & 1) * 4]);
                ldsm4(Bf[2 * np][0], Bf[2 * np][1], Bf[2 * np + 1][0], Bf[2 * np + 1][1], bd);
            }
#pragma unroll
            for (int mt = 0; mt < 4; mt++)
#pragma unroll
                for (int nt = 0; nt < 4; nt++)
                    mma8(acc[mt][nt], Af[mt], Bf[nt]);
        }

        if (more) {
            float* as = &As[(it + 1) & 1][lrow * P + lcol];
            *(float4*)(as)     = cvt4(ra0);
            *(float4*)(as + 4) = cvt4(ra1);
            float* bs = &Bs[(it + 1) & 1][lrow * P + lcol];
            *(float4*)(bs)     = cvt4(rb0);
            *(float4*)(bs + 4) = cvt4(rb1);
        }
    }

    const int g = L >> 2, tig = L & 3;
#pragma unroll
    for (int mt = 0; mt < 4; mt++) {
        const int r0 = m0 + mwb + mt * 16 + g;
#pragma unroll
        for (int nt = 0; nt < 4; nt++) {
            const int c = n0 + nwb + nt * 8 + tig * 2;
            float v0 = acc[mt][nt][0] + bias[c];
            float v1 = acc[mt][nt][1] + bias[c + 1];
            float v2 = acc[mt][nt][2] + bias[c];
            float v3 = acc[mt][nt][3] + bias[c + 1];
            if (EPI == 1) {
                v0 = gelu_exact(v0); v1 = gelu_exact(v1);
                v2 = gelu_exact(v2); v3 = gelu_exact(v3);
            }
            *(float2*)(C + (long long)r0 * ldc + c)       = make_float2(v0, v1);
            *(float2*)(C + (long long)(r0 + 8) * ldc + c) = make_float2(v2, v3);
        }
    }
}

__global__ __launch_bounds__(256) void k_tc_bias(
    const float* __restrict__ A, int lda, const float* __restrict__ B, int ldb,
    float* __restrict__ C, int ldc, int K, const float* __restrict__ bias)
{
    tc_nt_body<0>(A, lda, B, ldb, C, ldc, K, bias, blockIdx.y * 128, blockIdx.x * 128);
}
__global__ __launch_bounds__(256) void k_tc_bias_gelu(
    const float* __restrict__ A, int lda, const float* __restrict__ B, int ldb,
    float* __restrict__ C, int ldc, int K, const float* __restrict__ bias)
{
    tc_nt_body<1>(A, lda, B, ldb, C, ldc, K, bias, blockIdx.y * 128, blockIdx.x * 128);
}

// ---------------------------------------------------------------------------
// Attention pass 1: per-(z,s) softmax stats over t.
// Grid (16 s-blocks, 32 z), 256 thr. Warp w owns s-rows [w*16, w*16+16).
// SMEM: Ks[128][68], Qs[128][68] (dynamic, 69632 B)
// ---------------------------------------------------------------------------
__global__ __launch_bounds__(256) void k_attn_stats()
{
    extern __shared__ float dsm[];
    float* sK = dsm;               // 128*68
    float* sQ = dsm + 128 * 68;    // 128*68

    const int tid = threadIdx.x;
    const int w = tid >> 5, L = tid & 31;
    const int g = L >> 2, tig = L & 3;
    const int z = blockIdx.y, b = z >> 4, h = z & 15;
    const int s0 = blockIdx.x * 128;

    const float* Kg = g_qkv + (long long)b * SLEN * 3 * DMODEL + DMODEL + h * HDIM;
    const float* Qg = g_qkv + (long long)b * SLEN * 3 * DMODEL + h * HDIM;

    // stage K block (tf32-rounded)
    for (int i = tid; i < 128 * 16; i += 256) {
        const int r = i >> 4, c4 = (i & 15) * 4;
        *(float4*)(&sK[r * 68 + c4]) = cvt4(*(const float4*)(Kg + (long long)(s0 + r) * 3072 + c4));
    }
    __syncthreads();

    // A-operand fragments (K rows for this warp), held in registers
    const unsigned* KsU = (const unsigned*)sK;
    const int sw = w * 16;
    unsigned Af[8][4];
#pragma unroll
    for (int kf = 0; kf < 8; kf++) {
        const int base = (sw + g) * 68 + kf * 8 + tig;
        Af[kf][0] = KsU[base];
        Af[kf][1] = KsU[base + 8 * 68];
        Af[kf][2] = KsU[base + 4];
        Af[kf][3] = KsU[base + 8 * 68 + 4];
    }

    float m0 = -INFINITY, m1 = -INFINITY, Z0 = 0.0f, Z1 = 0.0f;
    const unsigned* QsU = (const unsigned*)sQ;

    for (int t0 = 0; t0 < SLEN; t0 += 128) {
        __syncthreads();
        for (int i = tid; i < 128 * 16; i += 256) {
            const int r = i >> 4, c4 = (i & 15) * 4;
            *(float4*)(&sQ[r * 68 + c4]) = cvt4(*(const float4*)(Qg + (long long)(t0 + r) * 3072 + c4));
        }
        __syncthreads();

        float acc[16][4];
#pragma unroll
        for (int nt = 0; nt < 16; nt++)
#pragma unroll
            for (int r = 0; r < 4; r++) acc[nt][r] = 0.0f;

#pragma unroll
        for (int nt = 0; nt < 16; nt++) {
#pragma unroll
            for (int kf = 0; kf < 8; kf++) {
                unsigned Bf[2];
                const int base = (nt * 8 + g) * 68 + kf * 8 + tig;
                Bf[0] = QsU[base];
                Bf[1] = QsU[base + 4];
                mma8(acc[nt], Af[kf], Bf);
            }
        }

        // online softmax update (scaled domain)
        float c0 = -INFINITY, c1 = -INFINITY;
#pragma unroll
        for (int nt = 0; nt < 16; nt++) {
            c0 = fmaxf(c0, fmaxf(acc[nt][0], acc[nt][1]));
            c1 = fmaxf(c1, fmaxf(acc[nt][2], acc[nt][3]));
        }
        c0 = qmax(c0) * 0.125f;
        c1 = qmax(c1) * 0.125f;
        const float nm0 = fmaxf(m0, c0);
        const float nm1 = fmaxf(m1, c1);
        float s0v = 0.0f, s1v = 0.0f;
#pragma unroll
        for (int nt = 0; nt < 16; nt++) {
            s0v += __expf(acc[nt][0] * 0.125f - nm0) + __expf(acc[nt][1] * 0.125f - nm0);
            s1v += __expf(acc[nt][2] * 0.125f - nm1) + __expf(acc[nt][3] * 0.125f - nm1);
        }
        s0v = qsum(s0v);
        s1v = qsum(s1v);
        Z0 = Z0 * __expf(m0 - nm0) + s0v; m0 = nm0;
        Z1 = Z1 * __expf(m1 - nm1) + s1v; m1 = nm1;
    }

    if (tig == 0) {
        g_stats[(size_t)z * SLEN + s0 + sw + g]     = make_float2(m0, Z0);
        g_stats[(size_t)z * SLEN + s0 + sw + g + 8] = make_float2(m1, Z1);
    }
}

// ---------------------------------------------------------------------------
// Attention pass 2: fused scores-recompute + softmax-apply + P@V + gelu/sqrt(S).
// Grid (16 t-blocks, 32 z), 256 thr, s-chunks of 64.
// SMEM (dynamic 105984 B): Qs[128][68] | Ks[64][68] | Vs[64][72] | Ps[128][68] | Ss[64]f2
// ---------------------------------------------------------------------------
__global__ __launch_bounds__(256) void k_attn_av()
{
    extern __shared__ float dsm[];
    float*  sQ = dsm;                       // 128*68 = 8704
    float*  sK = dsm + 8704;                // 64*68  = 4352
    float*  sV = dsm + 13056;               // 64*72  = 4608
    float*  sP = dsm + 17664;               // 128*68 = 8704
    float2* sS = (float2*)(dsm + 26368);    // 64

    const int tid = threadIdx.x;
    const int w = tid >> 5, L = tid & 31;
    const int g = L >> 2, tig = L & 3;
    const int wm = w & 3;        // t: 4 groups of 32
    const int wn = w >> 2;       // s (MMA1) / e (MMA2): 2 groups of 32
    const int twb = wm * 32;
    const int swb = wn * 32;
    const int z = blockIdx.y, b = z >> 4, h = z & 15;
    const int t0 = blockIdx.x * 128;

    const float* Qg = g_qkv + (long long)b * SLEN * 3 * DMODEL + h * HDIM;
    const float* Kg = g_qkv + (long long)b * SLEN * 3 * DMODEL + DMODEL + h * HDIM;
    const float* Vg = g_qkv + (long long)b * SLEN * 3 * DMODEL + 2 * DMODEL + h * HDIM;
    const float2* St = g_stats + (size_t)z * SLEN;

    // stage Q block once
    for (int i = tid; i < 128 * 16; i += 256) {
        const int r = i >> 4, c4 = (i & 15) * 4;
        *(float4*)(&sQ[r * 68 + c4]) = cvt4(*(const float4*)(Qg + (long long)(t0 + r) * 3072 + c4));
    }

    const unsigned* QsU = (const unsigned*)sQ;
    const unsigned* KsU = (const unsigned*)sK;
    const unsigned* VsU = (const unsigned*)sV;
    const unsigned* PsU = (const unsigned*)sP;

    float acc2[2][4][4];
#pragma unroll
    for (int i = 0; i < 2; i++)
#pragma unroll
        for (int j = 0; j < 4; j++)
#pragma unroll
            for (int r = 0; r < 4; r++) acc2[i][j][r] = 0.0f;

    for (int sc = 0; sc < SLEN; sc += 64) {
        __syncthreads();
        for (int i = tid; i < 64 * 16; i += 256) {
            const int r = i >> 4, c4 = (i & 15) * 4;
            *(float4*)(&sK[r * 68 + c4]) = cvt4(*(const float4*)(Kg + (long long)(sc + r) * 3072 + c4));
            *(float4*)(&sV[r * 72 + c4]) = cvt4(*(const float4*)(Vg + (long long)(sc + r) * 3072 + c4));
        }
        if (tid < 64) {
            float2 mz = St[sc + tid];
            sS[tid] = make_float2(mz.x, 1.0f / mz.y);
        }
        __syncthreads();

        // ---- MMA1: scores[t, s] = Q · K^T ----
        float acc1[2][4][4];
#pragma unroll
        for (int i = 0; i < 2; i++)
#pragma unroll
            for (int j = 0; j < 4; j++)
#pragma unroll
                for (int r = 0; r < 4; r++) acc1[i][j][r] = 0.0f;

#pragma unroll
        for (int mt = 0; mt < 2; mt++) {
            unsigned Af[8][4];
#pragma unroll
            for (int kf = 0; kf < 8; kf++) {
                const int base = (twb + mt * 16 + g) * 68 + kf * 8 + tig;
                Af[kf][0] = QsU[base];
                Af[kf][1] = QsU[base + 8 * 68];
                Af[kf][2] = QsU[base + 4];
                Af[kf][3] = QsU[base + 8 * 68 + 4];
            }
#pragma unroll
            for (int nt = 0; nt < 4; nt++) {
#pragma unroll
                for (int kf = 0; kf < 8; kf++) {
                    unsigned Bf[2];
                    const int base = (swb + nt * 8 + g) * 68 + kf * 8 + tig;
                    Bf[0] = KsU[base];
                    Bf[1] = KsU[base + 4];
                    mma8(acc1[mt][nt], Af[kf], Bf);
                }
            }
        }

        // ---- P = exp(score*scale - m_s) / Z_s, staged tf32 into sP ----
#pragma unroll
        for (int mt = 0; mt < 2; mt++) {
            const int tr = twb + mt * 16 + g;
#pragma unroll
            for (int nt = 0; nt < 4; nt++) {
                const int scol = swb + nt * 8 + tig * 2;
                const float2 st0 = sS[scol];
                const float2 st1 = sS[scol + 1];
                float p0 = __expf(acc1[mt][nt][0] * 0.125f - st0.x) * st0.y;
                float p1 = __expf(acc1[mt][nt][1] * 0.125f - st1.x) * st1.y;
                float p2 = __expf(acc1[mt][nt][2] * 0.125f - st0.x) * st0.y;
                float p3 = __expf(acc1[mt][nt][3] * 0.125f - st1.x) * st1.y;
                *(float2*)(&sP[tr * 68 + scol])       = make_float2(tf32r(p0), tf32r(p1));
                *(float2*)(&sP[(tr + 8) * 68 + scol]) = make_float2(tf32r(p2), tf32r(p3));
            }
        }
        __syncthreads();

        // ---- MMA2: post[t, e] += P · V ----
#pragma unroll
        for (int mt = 0; mt < 2; mt++) {
            unsigned Af[8][4];
#pragma unroll
            for (int kf = 0; kf < 8; kf++) {
                const int base = (twb + mt * 16 + g) * 68 + kf * 8 + tig;
                Af[kf][0] = PsU[base];
                Af[kf][1] = PsU[base + 8 * 68];
                Af[kf][2] = PsU[base + 4];
                Af[kf][3] = PsU[base + 8 * 68 + 4];
            }
#pragma unroll
            for (int nt = 0; nt < 4; nt++) {
#pragma unroll
                for (int kf = 0; kf < 8; kf++) {
                    unsigned Bf[2];
                    const int base = (kf * 8 + tig) * 72 + swb + nt * 8 + g;
                    Bf[0] = VsU[base];
                    Bf[1] = VsU[base + 4 * 72];
                    mma8(acc2[mt][nt], Af[kf], Bf);
                }
            }
        }
    }

    // epilogue: gelu(post)/sqrt(S)
    const float inv_sqrt_s = 0.022097086912079608f;
    float* C = g_post + (long long)b * SLEN * DMODEL + h * HDIM;
#pragma unroll
    for (int mt = 0; mt < 2; mt++) {
        const int tr = t0 + twb + mt * 16 + g;
#pragma unroll
        for (int nt = 0; nt < 4; nt++) {
            const int e = swb + nt * 8 + tig * 2;
            float v0 = gelu_exact(acc2[mt][nt][0]) * inv_sqrt_s;
            float v1 = gelu_exact(acc2[mt][nt][1]) * inv_sqrt_s;
            float v2 = gelu_exact(acc2[mt][nt][2]) * inv_sqrt_s;
            float v3 = gelu_exact(acc2[mt][nt][3]) * inv_sqrt_s;
            *(float2*)(C + (long long)tr * DMODEL + e)       = make_float2(v0, v1);
            *(float2*)(C + (long long)(tr + 8) * DMODEL + e) = make_float2(v2, v3);
        }
    }
}

// ---------------------------------------------------------------------------
// out[r,:] = LayerNorm(x1[r,:] + x2[r,:]) * g + b
// ---------------------------------------------------------------------------
__global__ __launch_bounds__(256) void k_add_ln(
    const float* __restrict__ x1, const float* __restrict__ x2,
    const float* __restrict__ gg, const float* __restrict__ bb,
    float* __restrict__ out)
{
    const long long base = (long long)blockIdx.x * DMODEL;
    const int tid = threadIdx.x;
    __shared__ float rs[256], rs2[256];

    float v[4];
    float s = 0.0f, s2 = 0.0f;
#pragma unroll
    for (int i = 0; i < 4; i++) {
        const int c = tid + i * 256;
        const float a = x1[base + c] + x2[base + c];
        v[i] = a; s += a; s2 += a * a;
    }
    rs[tid] = s; rs2[tid] = s2; __syncthreads();
    for (int st = 128; st > 0; st >>= 1) {
        if (tid < st) { rs[tid] += rs[tid + st]; rs2[tid] += rs2[tid + st]; }
        __syncthreads();
    }
    const float mu  = rs[0] * (1.0f / DMODEL);
    const float var = rs2[0] * (1.0f / DMODEL) - mu * mu;
    const float r   = rsqrtf(var + 1e-5f);
#pragma unroll
    for (int i = 0; i < 4; i++) {
        const int c = tid + i * 256;
        out[base + c] = (v[i] - mu) * r * gg[c] + bb[c];
    }
}

// ---------------------------------------------------------------------------
// Launch
// ---------------------------------------------------------------------------
extern "C" void kernel_launch(void* const* d_in, const int* in_sizes, int n_in,
                              void* d_out, int out_size)
{
    (void)in_sizes; (void)n_in; (void)out_size;
    const float* src       = (const float*)d_in[0];
    const float* in_proj_w = (const float*)d_in[1];
    const float* in_proj_b = (const float*)d_in[2];
    const float* out_w     = (const float*)d_in[3];
    const float* out_b     = (const float*)d_in[4];
    const float* lin1_w    = (const float*)d_in[5];
    const float* lin1_b    = (const float*)d_in[6];
    const float* lin2_w    = (const float*)d_in[7];
    const float* lin2_b    = (const float*)d_in[8];
    const float* ln1_g     = (const float*)d_in[9];
    const float* ln1_bb    = (const float*)d_in[10];
    const float* ln2_g     = (const float*)d_in[11];
    const float* ln2_bb    = (const float*)d_in[12];
    float* out = (float*)d_out;

    float *qkv, *post, *attnout, *x, *ff1, *ff2;
    cudaGetSymbolAddress((void**)&qkv,     g_qkv);
    cudaGetSymbolAddress((void**)&post,    g_post);
    cudaGetSymbolAddress((void**)&attnout, g_attnout);
    cudaGetSymbolAddress((void**)&x,       g_x);
    cudaGetSymbolAddress((void**)&ff1,     g_ff1);
    cudaGetSymbolAddress((void**)&ff2,     g_ff2);

    const int smemA = 2 * 128 * 68 * 4;                     // 69632
    const int smemB = (26368 + 128) * 4;                    // 105984
    cudaFuncSetAttribute(k_attn_stats, cudaFuncAttributeMaxDynamicSharedMemorySize, smemA);
    cudaFuncSetAttribute(k_attn_av,    cudaFuncAttributeMaxDynamicSharedMemorySize, smemB);

    const dim3 blk(256);

    // 1. QKV projection
    k_tc_bias<<<dim3(3 * DMODEL / 128, TOKS / 128), blk>>>(
        src, DMODEL, in_proj_w, DMODEL, qkv, 3 * DMODEL, DMODEL, in_proj_b);

    // 2. softmax stats per (z, s)
    k_attn_stats<<<dim3(SLEN / 128, BATCH * NHEADS), blk, smemA>>>();

    // 3. fused attention: recompute scores, apply softmax, @V, gelu/sqrt(S)
    k_attn_av<<<dim3(SLEN / 128, BATCH * NHEADS), blk, smemB>>>();

    // 4. attn output projection
    k_tc_bias<<<dim3(DMODEL / 128, TOKS / 128), blk>>>(
        post, DMODEL, out_w, DMODEL, attnout, DMODEL, DMODEL, out_b);

    // 5. x = LN1(src + attnout)
    k_add_ln<<<TOKS, 256>>>(src, attnout, ln1_g, ln1_bb, x);

    // 6. ff1 = gelu(x @ lin1_w^T + b)
    k_tc_bias_gelu<<<dim3(DFF / 128, TOKS / 128), blk>>>(
        x, DMODEL, lin1_w, DMODEL, ff1, DFF, DMODEL, lin1_b);

    // 7. ff2 = ff1 @ lin2_w^T + b
    k_tc_bias<<<dim3(DMODEL / 128, TOKS / 128), blk>>>(
        ff1, DFF, lin2_w, DFF, ff2, DMODEL, DFF, lin2_b);

    // 8. out = LN2(x + ff2)
    k_add_ln<<<TOKS, 256>>>(x, ff2, ln2_g, ln2_bb, out);
}